// round 17
// baseline (speedup 1.0000x reference)
#include <cuda_runtime.h>
#include <cuda_bf16.h>
#include <math.h>

#define NB 4096
#define NL 8192
#define R4 (NL / 4)                 // 2048 float4 groups per row
#define NT 128
#define GRID2 1776                  // 12 CTAs * 148 SMs: exactly one wave
#define FXSCALE 16777216.0f         // 2^24 fixed-point scale for loss
#define LG2CLAMP (-144.26950408889634f)   // -100 / ln(2)
#define LN2F 0.6931471805599453f

__device__ int      g_cum[NB + 1];  // exclusive prefix of per-row float4-group counts
__device__ int      g_valid_tot;    // sum(lengths)  (overwritten each launch)
__device__ unsigned long long g_loss_fx = 0;
__device__ int      g_tp_acc = 0;
__device__ int      g_tn_acc = 0;
__device__ int      g_gp_acc = 0;
__device__ unsigned g_done   = 0;

// ---------------- Phase 1: scan of group counts ----------------
__global__ void __launch_bounds__(1024) scan_kernel(const int* __restrict__ lengths) {
    const int t = threadIdx.x;
    const int lane = t & 31, wid = t >> 5;
    int l0 = lengths[4 * t], l1 = lengths[4 * t + 1],
        l2 = lengths[4 * t + 2], l3 = lengths[4 * t + 3];
    int n0 = l0 >> 2, n1 = l1 >> 2, n2 = l2 >> 2, n3 = l3 >> 2;
    int tot = n0 + n1 + n2 + n3;

    // inclusive warp scan
    int x = tot;
    #pragma unroll
    for (int s = 1; s < 32; s <<= 1) {
        int y = __shfl_up_sync(0xffffffffu, x, s);
        if (lane >= s) x += y;
    }
    __shared__ int wsum[32];
    if (lane == 31) wsum[wid] = x;
    __syncthreads();
    if (wid == 0) {
        int w = wsum[lane];
        #pragma unroll
        for (int s = 1; s < 32; s <<= 1) {
            int y = __shfl_up_sync(0xffffffffu, w, s);
            if (lane >= s) w += y;
        }
        wsum[lane] = w;
    }
    __syncthreads();
    int excl = x - tot + (wid ? wsum[wid - 1] : 0);
    g_cum[4 * t]     = excl;
    g_cum[4 * t + 1] = excl + n0;
    g_cum[4 * t + 2] = excl + n0 + n1;
    g_cum[4 * t + 3] = excl + n0 + n1 + n2;
    if (t == 1023) g_cum[NB] = excl + tot;

    // total valid elements
    int lv = l0 + l1 + l2 + l3;
    #pragma unroll
    for (int s = 16; s > 0; s >>= 1) lv += __shfl_down_sync(0xffffffffu, lv, s);
    __shared__ int vsum[32];
    if (lane == 0) vsum[wid] = lv;
    __syncthreads();
    if (t == 0) {
        int V = 0;
        #pragma unroll
        for (int w = 0; w < 32; w++) V += vsum[w];
        g_valid_tot = V;
    }
}

// Cheap counters (exact: per-thread counts small ints in f32):
//   gp = sum(t);  tp = sum(t | p>0.5);  tn = count(p<=0.5) - sum(t | p<=0.5)
__device__ __forceinline__ void acc_elem(float p, float t, float inv, float& loss,
                                         float& gpf, float& tpf, float& snf, int& nnb) {
    float x = 1.0f - fabsf(t - p);                       // == t ? p : 1-p (exact)
    loss = __fmaf_rn(fmaxf(__log2f(x), LG2CLAMP), inv, loss);  // lg2 domain
    bool pb = (p > 0.5f);
    gpf += t;
    if (pb)  tpf += t;
    else   { nnb++; snf += t; }
}

// ---------------- Phase 2: uniform balanced main ----------------
__global__ void __launch_bounds__(NT) main_kernel(const float* __restrict__ pred,
                                                  const float* __restrict__ truth,
                                                  const int*   __restrict__ lengths,
                                                  float* __restrict__ out,
                                                  int out_size) {
    const int b = blockIdx.x, t = threadIdx.x;
    const int G4 = g_cum[NB];
    const int W  = (G4 + GRID2 - 1) / GRID2;
    const int gbeg = b * W;
    const int gend = min(gbeg + W, G4);

    float loss = 0.0f;
    float gpf = 0.0f, tpf = 0.0f, snf = 0.0f;
    int nnb = 0;

    const float4* __restrict__ p4 = reinterpret_cast<const float4*>(pred);
    const float4* __restrict__ t4 = reinterpret_cast<const float4*>(truth);

    int g = gbeg + t;
    if (g < gend) {
        // binary search: largest row with cum[row] <= g
        int lo = 0, hi = NB;
        while (hi - lo > 1) {
            int mid = (lo + hi) >> 1;
            if (g_cum[mid] <= g) lo = mid; else hi = mid;
        }
        int row = lo;
        int cbase = g_cum[row], cnext = g_cum[row + 1];
        float inv = __fdividef(1.0f, (float)__ldg(lengths + row));

        #pragma unroll 2
        for (; g < gend; g += NT) {
            if (g >= cnext) {
                do { row++; cbase = cnext; cnext = g_cum[row + 1]; } while (g >= cnext);
                inv = __fdividef(1.0f, (float)__ldg(lengths + row));
            }
            const size_t idx = (size_t)row * R4 + (g - cbase);
            float4 p = p4[idx];
            float4 tv = t4[idx];
            acc_elem(p.x, tv.x, inv, loss, gpf, tpf, snf, nnb);
            acc_elem(p.y, tv.y, inv, loss, gpf, tpf, snf, nnb);
            acc_elem(p.z, tv.z, inv, loss, gpf, tpf, snf, nnb);
            acc_elem(p.w, tv.w, inv, loss, gpf, tpf, snf, nnb);
        }
    }

    // row tails (len % 4 elements): 3 rows per block, slots = 3 rows x 3 elems
    if (t < 9) {
        int rr = b * 3 + t / 3;
        if (rr < NB) {
            int len = __ldg(lengths + rr);
            int k = t % 3;
            if (k < (len & 3)) {
                size_t e = (size_t)rr * NL + (len & ~3) + k;
                float inv = __fdividef(1.0f, (float)len);
                acc_elem(pred[e], truth[e], inv, loss, gpf, tpf, snf, nnb);
            }
        }
    }

    int gp = (int)gpf;
    int tp = (int)tpf;
    int tn = nnb - (int)snf;

    // ---- block reduce (4 warps) ----
    #pragma unroll
    for (int s = 16; s > 0; s >>= 1) {
        loss += __shfl_down_sync(0xffffffffu, loss, s);
        tp   += __shfl_down_sync(0xffffffffu, tp,   s);
        tn   += __shfl_down_sync(0xffffffffu, tn,   s);
        gp   += __shfl_down_sync(0xffffffffu, gp,   s);
    }
    __shared__ float s_l[NT / 32];
    __shared__ int   s_tp[NT / 32], s_tn[NT / 32], s_gp[NT / 32];
    const int wid = t >> 5, lid = t & 31;
    if (lid == 0) { s_l[wid] = loss; s_tp[wid] = tp; s_tn[wid] = tn; s_gp[wid] = gp; }
    __syncthreads();

    if (t == 0) {
        float L = 0.0f; int a = 0, c = 0, d = 0;
        #pragma unroll
        for (int w = 0; w < NT / 32; w++) { L += s_l[w]; a += s_tp[w]; c += s_tn[w]; d += s_gp[w]; }
        float S = -L * LN2F;   // lg2 -> ln; loss already has 1/len folded in
        atomicAdd(&g_loss_fx, (unsigned long long)__float2ll_rn(S * FXSCALE));
        if (a) atomicAdd(&g_tp_acc, a);
        if (c) atomicAdd(&g_tn_acc, c);
        if (d) atomicAdd(&g_gp_acc, d);
        __threadfence();
        unsigned done = atomicAdd(&g_done, 1u);
        if (done == (unsigned)(GRID2 - 1)) {
            unsigned long long fx = atomicAdd(&g_loss_fx, 0ULL);
            int TP = atomicAdd(&g_tp_acc, 0);
            int TN = atomicAdd(&g_tn_acc, 0);
            int GP = atomicAdd(&g_gp_acc, 0);
            int V  = g_valid_tot;
            int GN = V - GP;
            if (GP < 1) GP = 1;
            if (GN < 1) GN = 1;
            out[0] = (float)((double)fx / (double)FXSCALE / (double)NB);
            if (out_size > 1) out[1] = ((float)TP / (float)GP) * ((float)TN / (float)GN);
            g_loss_fx = 0ULL;
            g_tp_acc = 0; g_tn_acc = 0; g_gp_acc = 0;
            g_done = 0;
        }
    }
}

extern "C" void kernel_launch(void* const* d_in, const int* in_sizes, int n_in,
                              void* d_out, int out_size) {
    const float* pred    = (const float*)d_in[0];
    const float* truth   = (const float*)d_in[1];
    const int*   lengths = (const int*)d_in[2];
    float* out = (float*)d_out;

    scan_kernel<<<1, 1024>>>(lengths);
    main_kernel<<<GRID2, NT>>>(pred, truth, lengths, out, out_size);
}